// round 4
// baseline (speedup 1.0000x reference)
#include <cuda_runtime.h>
#include <cuda_bf16.h>
#include <math.h>
#include <float.h>

// Problem constants (fixed shapes from reference)
#define Bq   4
#define Tq   16
#define Sq   4096
#define Hq   32
#define KVq  8
#define Dq   128
#define DIMq 4096
#define HD   (Hq*Dq)          // 4096
#define KVD  (KVq*Dq)         // 1024
#define NTOT (HD + 2*KVD)     // 6144
#define M64  (Bq*Tq)          // 64
#define GQ   (Hq/KVq)         // 4
#define AROWS 64              // GQ*Tq rows per (b,kv)
#define NSPLIT 16
#define STILE 32
#define SCALE_F 0.08838834764831843f   // 1/sqrt(128)
#define SPLITK 4

// ---------------- scratch (static device globals; no allocation) ------------
__device__ float g_qkvp[SPLITK][M64 * NTOT];               // 6 MB partials
__device__ float g_outp[SPLITK][M64 * DIMq];               // 4 MB partials
__device__ float g_qkv [M64 * NTOT];                       // 1.5 MB   [m][n]
__device__ float g_qatt[Bq*KVq*AROWS*Dq];                  // 1 MB     roped+scaled q
__device__ float g_knew[M64*KVq*Dq];                       // 256 KB   roped new k
__device__ float g_pacc[(size_t)NSPLIT*Bq*KVq*AROWS*Dq];   // 16 MB
__device__ float g_pm  [NSPLIT*Bq*KVq*AROWS];
__device__ float g_pl  [NSPLIT*Bq*KVq*AROWS];
__device__ float g_y   [M64 * HD];                         // 1 MB

// ================= tensor-core GEMM (tf32 mma.sync), split-K ================
// C[64][64] partial = A[64][kslice] * W[64n][kslice]^T.
// 8 warps (2m x 4n), warp tile 32x16, mma m16n8k8, BK=32, 4-stage cp.async.
#define BKg      32
#define GSTAGES  4
#define GSTRIDE  36
#define GSTG_FLT (2 * 64 * GSTRIDE)
#define GEMM_SMEM_BYTES (GSTAGES * GSTG_FLT * 4)
#define GK       4096
#define GNKS     (GK / BKg / SPLITK)       // 32 K-steps per split

__device__ __forceinline__ unsigned smem_u32(const void* p) {
    unsigned a;
    asm("{ .reg .u64 t; cvta.to.shared.u64 t, %1; cvt.u32.u64 %0, t; }"
        : "=r"(a) : "l"(p));
    return a;
}
__device__ __forceinline__ unsigned f2tf32(float x) {
    unsigned u; asm("cvt.rna.tf32.f32 %0, %1;" : "=r"(u) : "f"(x)); return u;
}
__device__ __forceinline__ void mma_tf32(float c[4], const unsigned a[4], const unsigned b[2]) {
    asm volatile(
        "mma.sync.aligned.m16n8k8.row.col.f32.tf32.tf32.f32 "
        "{%0,%1,%2,%3}, {%4,%5,%6,%7}, {%8,%9}, {%0,%1,%2,%3};\n"
        : "+f"(c[0]), "+f"(c[1]), "+f"(c[2]), "+f"(c[3])
        : "r"(a[0]), "r"(a[1]), "r"(a[2]), "r"(a[3]), "r"(b[0]), "r"(b[1]));
}
__device__ __forceinline__ void cpasync16(unsigned saddr, const float* g) {
    asm volatile("cp.async.ca.shared.global [%0], [%1], 16;" :: "r"(saddr), "l"(g));
}

__device__ __forceinline__ void gemm_tile_mma(const float* __restrict__ A,
                                              const float* __restrict__ W,
                                              float* __restrict__ Cbase,
                                              int ldc, int kbeg) {
    extern __shared__ float smf[];
    const int tid  = threadIdx.x;
    const int lane = tid & 31;
    const int wid  = tid >> 5;
    const int gid  = lane >> 2;      // 0..7
    const int ctg  = lane & 3;       // 0..3
    const int wm   = wid & 1;
    const int wn   = wid >> 1;
    const int frow = tid >> 2;       // 0..63
    const int fk   = (tid & 3) * 8;
    const unsigned sbase = smem_u32(smf);

    float acc[2][2][4];
#pragma unroll
    for (int mi = 0; mi < 2; mi++)
#pragma unroll
        for (int ni = 0; ni < 2; ni++)
#pragma unroll
            for (int j = 0; j < 4; j++) acc[mi][ni][j] = 0.f;

#pragma unroll
    for (int s = 0; s < GSTAGES - 1; s++) {
        unsigned sa = sbase + (unsigned)(s * GSTG_FLT + frow * GSTRIDE + fk) * 4u;
        unsigned sw = sa + 64u * GSTRIDE * 4u;
        const float* ga = A + (size_t)frow * GK + kbeg + s * BKg + fk;
        const float* gw = W + (size_t)frow * GK + kbeg + s * BKg + fk;
        cpasync16(sa, ga);       cpasync16(sa + 16, ga + 4);
        cpasync16(sw, gw);       cpasync16(sw + 16, gw + 4);
        asm volatile("cp.async.commit_group;");
    }

    for (int i = 0; i < GNKS; i++) {
        asm volatile("cp.async.wait_group 2;");
        __syncthreads();
        const float* As = smf + (i & 3) * GSTG_FLT;
        const float* Ws = As + 64 * GSTRIDE;

#pragma unroll
        for (int ks = 0; ks < 4; ks++) {
            const int k = ks * 8;
            unsigned af[2][4], bf[2][2];
#pragma unroll
            for (int mi = 0; mi < 2; mi++) {
                int r = wm * 32 + mi * 16 + gid;
                af[mi][0] = f2tf32(As[r * GSTRIDE + k + ctg]);
                af[mi][1] = f2tf32(As[(r + 8) * GSTRIDE + k + ctg]);
                af[mi][2] = f2tf32(As[r * GSTRIDE + k + ctg + 4]);
                af[mi][3] = f2tf32(As[(r + 8) * GSTRIDE + k + ctg + 4]);
            }
#pragma unroll
            for (int ni = 0; ni < 2; ni++) {
                int n = wn * 16 + ni * 8 + gid;
                bf[ni][0] = f2tf32(Ws[n * GSTRIDE + k + ctg]);
                bf[ni][1] = f2tf32(Ws[n * GSTRIDE + k + ctg + 4]);
            }
#pragma unroll
            for (int mi = 0; mi < 2; mi++)
#pragma unroll
                for (int ni = 0; ni < 2; ni++)
                    mma_tf32(acc[mi][ni], af[mi], bf[ni]);
        }

        if (i + GSTAGES - 1 < GNKS) {
            int s = (i + 3) & 3;
            int k0 = kbeg + (i + 3) * BKg;
            unsigned sa = sbase + (unsigned)(s * GSTG_FLT + frow * GSTRIDE + fk) * 4u;
            unsigned sw = sa + 64u * GSTRIDE * 4u;
            const float* ga = A + (size_t)frow * GK + k0 + fk;
            const float* gw = W + (size_t)frow * GK + k0 + fk;
            cpasync16(sa, ga);       cpasync16(sa + 16, ga + 4);
            cpasync16(sw, gw);       cpasync16(sw + 16, gw + 4);
            asm volatile("cp.async.commit_group;");
        } else {
            asm volatile("cp.async.commit_group;");
        }
    }

#pragma unroll
    for (int mi = 0; mi < 2; mi++)
#pragma unroll
        for (int ni = 0; ni < 2; ni++) {
            int r0 = wm * 32 + mi * 16 + gid;
            int c0 = wn * 16 + ni * 8 + 2 * ctg;
            *reinterpret_cast<float2*>(&Cbase[(size_t)r0 * ldc + c0]) =
                make_float2(acc[mi][ni][0], acc[mi][ni][1]);
            *reinterpret_cast<float2*>(&Cbase[(size_t)(r0 + 8) * ldc + c0]) =
                make_float2(acc[mi][ni][2], acc[mi][ni][3]);
        }
}

// ---------------- QKV projection (split-K partials) -------------------------
__global__ void qkv_kernel(const float* __restrict__ x,
                           const float* __restrict__ wq,
                           const float* __restrict__ wk,
                           const float* __restrict__ wv) {
    int n0 = blockIdx.x * 64;
    int sp = blockIdx.y;
    const float* W;
    if (n0 < HD)            W = wq + (size_t)n0 * DIMq;
    else if (n0 < HD + KVD) W = wk + (size_t)(n0 - HD) * DIMq;
    else                    W = wv + (size_t)(n0 - HD - KVD) * DIMq;
    gemm_tile_mma(x, W, g_qkvp[sp] + n0, NTOT, sp * (GK / SPLITK));
}

__global__ void reduce_qkv_kernel() {
    int i = blockIdx.x * 256 + threadIdx.x;           // float4 index
    if (i >= M64 * NTOT / 4) return;
    float4 a = reinterpret_cast<const float4*>(g_qkvp[0])[i];
    float4 b = reinterpret_cast<const float4*>(g_qkvp[1])[i];
    float4 c = reinterpret_cast<const float4*>(g_qkvp[2])[i];
    float4 d = reinterpret_cast<const float4*>(g_qkvp[3])[i];
    reinterpret_cast<float4*>(g_qkv)[i] =
        make_float4(a.x+b.x+c.x+d.x, a.y+b.y+c.y+d.y,
                    a.z+b.z+c.z+d.z, a.w+b.w+c.w+d.w);
}

// ---------------- output projection (split-K partials) ----------------------
__global__ void out_kernel(const float* __restrict__ wo) {
    int n0 = blockIdx.x * 64;
    int sp = blockIdx.y;
    gemm_tile_mma(g_y, wo + (size_t)n0 * DIMq, g_outp[sp] + n0, DIMq,
                  sp * (GK / SPLITK));
}

__global__ void reduce_out_kernel(float* __restrict__ out) {
    int i = blockIdx.x * 256 + threadIdx.x;
    if (i >= M64 * DIMq / 4) return;
    float4 a = reinterpret_cast<const float4*>(g_outp[0])[i];
    float4 b = reinterpret_cast<const float4*>(g_outp[1])[i];
    float4 c = reinterpret_cast<const float4*>(g_outp[2])[i];
    float4 d = reinterpret_cast<const float4*>(g_outp[3])[i];
    reinterpret_cast<float4*>(out)[i] =
        make_float4(a.x+b.x+c.x+d.x, a.y+b.y+c.y+d.y,
                    a.z+b.z+c.z+d.z, a.w+b.w+c.w+d.w);
}

// ---------------- RoPE: q -> g_qatt (scaled), k -> g_knew -------------------
#define QPAIRS (M64*Hq*(Dq/2))   // 131072
#define KPAIRS (M64*KVq*(Dq/2))  // 32768
__global__ void rope_kernel(const float* __restrict__ fc, const float* __restrict__ fs) {
    int idx = blockIdx.x * blockDim.x + threadIdx.x;
    if (idx < QPAIRS) {
        int i = idx & 63;
        int h = (idx >> 6) & (Hq - 1);
        int m = idx >> 11;            // b*T + t
        int t = m & (Tq - 1), b = m >> 4;
        float c = fc[t * 64 + i], s = fs[t * 64 + i];
        const float* p = g_qkv + (size_t)m * NTOT + h * Dq + 2 * i;
        float x0 = p[0], x1 = p[1];
        int kv = h >> 2, hl = h & 3;
        float* q = g_qatt + ((((size_t)b * KVq + kv) * AROWS) + hl * Tq + t) * Dq + 2 * i;
        q[0] = (x0 * c - x1 * s) * SCALE_F;
        q[1] = (x0 * s + x1 * c) * SCALE_F;
    } else if (idx < QPAIRS + KPAIRS) {
        int j = idx - QPAIRS;
        int i = j & 63;
        int kv = (j >> 6) & (KVq - 1);
        int m = j >> 9;
        int t = m & (Tq - 1);
        float c = fc[t * 64 + i], s = fs[t * 64 + i];
        const float* p = g_qkv + (size_t)m * NTOT + HD + kv * Dq + 2 * i;
        float x0 = p[0], x1 = p[1];
        float* k = g_knew + ((size_t)m * KVq + kv) * Dq + 2 * i;
        k[0] = x0 * c - x1 * s;
        k[1] = x0 * s + x1 * c;
    }
}

// ---------------- flash attention, split-KV ---------------------------------
// Padded strides (multiple of 4 for float4, row stride 132 -> conflict-free)
#define QSTR 132
#define KSTR 132
#define ATTN_SMEM_FLOATS (64*QSTR + 32*KSTR + 32*128 + 64*STILE + 3*64)
__global__ void attn_kernel(const float* __restrict__ k_cache,
                            const float* __restrict__ v_cache,
                            const int* __restrict__ input_pos) {
    extern __shared__ float sm[];
    float* Qs   = sm;                   // [64][132]
    float* Ks   = Qs + 64 * QSTR;       // [32][132]
    float* Vs   = Ks + 32 * KSTR;       // [32][128]
    float* Ps   = Vs + 32 * 128;        // [64][32]
    float* rowm = Ps + 64 * STILE;
    float* rowl = rowm + 64;
    float* rowsc = rowl + 64;
    __shared__ int pos_s[Tq];

    const int tid = threadIdx.x;
    const int bk = blockIdx.x % (Bq * KVq);
    const int split = blockIdx.x / (Bq * KVq);
    const int b = bk / KVq, kv = bk % KVq;

    if (tid < Tq) pos_s[tid] = input_pos[tid];
    const float* qsrc = g_qatt + ((size_t)b * KVq + kv) * AROWS * Dq;
    for (int e = tid; e < AROWS * Dq; e += 256) {
        int r = e >> 7, d = e & 127;
        Qs[r * QSTR + d] = qsrc[e];
    }
    if (tid < AROWS) { rowm[tid] = -FLT_MAX; rowl[tid] = 0.f; }
    __syncthreads();

    const int limit = pos_s[Tq - 1] + 1;
    const int chunk = (limit + NSPLIT - 1) / NSPLIT;
    const int sbeg = split * chunk;
    const int send = min(sbeg + chunk, limit);
    const int start_pos = pos_s[0];

    float acc[32];
#pragma unroll
    for (int i = 0; i < 32; i++) acc[i] = 0.f;
    const int myd = tid & 127;
    const int roff = tid >> 7;   // 0/1

    for (int s0 = sbeg; s0 < send; s0 += STILE) {
        // ---- load K/V tile ----
        for (int e = tid; e < STILE * Dq; e += 256) {
            int sl = e >> 7, d = e & 127;
            int s = s0 + sl;
            float kval = 0.f, vval = 0.f;
            if (s < send) {
                if (s >= start_pos && s < start_pos + Tq) {
                    int mi = b * Tq + (s - start_pos);
                    kval = g_knew[((size_t)mi * KVq + kv) * Dq + d];
                    vval = g_qkv[(size_t)mi * NTOT + HD + KVD + kv * Dq + d];
                } else {
                    size_t base = (((size_t)b * Sq + s) * KVq + kv) * Dq + d;
                    kval = k_cache[base];
                    vval = v_cache[base];
                }
            }
            Ks[sl * KSTR + d] = kval;
            Vs[sl * 128 + d] = vval;
        }
        __syncthreads();

        // ---- scores: thread computes 2 rows x 4 keys, float4 k-loop ----
        {
            const int rg = tid >> 3;   // 0..31
            const int sg = tid & 7;    // 0..7
            float sc0[4] = {0.f,0.f,0.f,0.f};
            float sc1[4] = {0.f,0.f,0.f,0.f};
            const float* q0 = &Qs[(rg * 2 + 0) * QSTR];
            const float* q1 = &Qs[(rg * 2 + 1) * QSTR];
#pragma unroll 4
            for (int k = 0; k < Dq; k += 4) {
                float4 a0 = *reinterpret_cast<const float4*>(&q0[k]);
                float4 a1 = *reinterpret_cast<const float4*>(&q1[k]);
#pragma unroll
                for (int j = 0; j < 4; j++) {
                    float4 bb = *reinterpret_cast<const float4*>(
                        &Ks[(sg * 4 + j) * KSTR + k]);
                    sc0[j] += a0.x*bb.x + a0.y*bb.y + a0.z*bb.z + a0.w*bb.w;
                    sc1[j] += a1.x*bb.x + a1.y*bb.y + a1.z*bb.z + a1.w*bb.w;
                }
            }
#pragma unroll
            for (int j = 0; j < 4; j++) {
                int s = s0 + sg * 4 + j;
                int r0 = rg * 2, r1 = rg * 2 + 1;
                int ok = (s < send);
                Ps[r0 * STILE + sg * 4 + j] =
                    (ok && s <= pos_s[r0 & 15]) ? sc0[j] : -FLT_MAX;
                Ps[r1 * STILE + sg * 4 + j] =
                    (ok && s <= pos_s[r1 & 15]) ? sc1[j] : -FLT_MAX;
            }
        }
        __syncthreads();

        // ---- online softmax per row ----
        if (tid < AROWS) {
            int r = tid;
            float mold = rowm[r];
            float mx = mold;
#pragma unroll
            for (int j = 0; j < STILE; j++) mx = fmaxf(mx, Ps[r * STILE + j]);
            float scl = __expf(mold - mx);
            float lsum = rowl[r] * scl;
#pragma unroll
            for (int j = 0; j < STILE; j++) {
                float p = __expf(Ps[r * STILE + j] - mx);
                Ps[r * STILE + j] = p;
                lsum += p;
            }
            rowm[r] = mx; rowl[r] = lsum; rowsc[r] = scl;
        }
        __syncthreads();

        // ---- rescale + accumulate P@V (float4 over keys) ----
#pragma unroll
        for (int i = 0; i < 32; i++) acc[i] *= rowsc[2 * i + roff];
#pragma unroll
        for (int sl4 = 0; sl4 < STILE; sl4 += 4) {
            float v0 = Vs[(sl4 + 0) * 128 + myd];
            float v1 = Vs[(sl4 + 1) * 128 + myd];
            float v2 = Vs[(sl4 + 2) * 128 + myd];
            float v3 = Vs[(sl4 + 3) * 128 + myd];
#pragma unroll
            for (int i = 0; i < 32; i++) {
                float4 p = *reinterpret_cast<const float4*>(
                    &Ps[(2 * i + roff) * STILE + sl4]);
                acc[i] += p.x * v0 + p.y * v1 + p.z * v2 + p.w * v3;
            }
        }
        __syncthreads();
    }

    float* pbase = g_pacc + ((size_t)split * Bq * KVq + bk) * AROWS * Dq;
#pragma unroll
    for (int i = 0; i < 32; i++)
        pbase[(2 * i + roff) * Dq + myd] = acc[i];
    if (tid < AROWS) {
        int o = (split * Bq * KVq + bk) * AROWS + tid;
        g_pm[o] = rowm[tid];
        g_pl[o] = rowl[tid];
    }
}

// ---------------- combine splits (log-sum-exp merge) ------------------------
__global__ void combine_kernel() {
    int idx = blockIdx.x * 256 + threadIdx.x;
    if (idx >= Bq * KVq * AROWS * Dq) return;
    int d = idx & 127;
    int r = (idx >> 7) & 63;
    int bk = idx >> 13;
    float M = -FLT_MAX;
#pragma unroll
    for (int sp = 0; sp < NSPLIT; sp++)
        M = fmaxf(M, g_pm[(sp * Bq * KVq + bk) * AROWS + r]);
    float L = 0.f, Y = 0.f;
#pragma unroll
    for (int sp = 0; sp < NSPLIT; sp++) {
        int o = (sp * Bq * KVq + bk) * AROWS + r;
        float w = __expf(g_pm[o] - M);
        L += g_pl[o] * w;
        Y += g_pacc[(size_t)o * Dq + d] * w;
    }
    float y = Y / L;
    int b = bk >> 3, kv = bk & 7;
    int hl = r >> 4, t = r & 15;
    int h = kv * GQ + hl;
    int m = b * Tq + t;
    g_y[(size_t)m * HD + h * Dq + d] = y;
}

// ---------------- launch -----------------------------------------------------
extern "C" void kernel_launch(void* const* d_in, const int* in_sizes, int n_in,
                              void* d_out, int out_size) {
    const float* x  = (const float*)d_in[0];
    const float* fc = (const float*)d_in[1];
    const float* fs = (const float*)d_in[2];
    const int*  pos = (const int*)  d_in[3];
    // d_in[4] attn_mask unused (mask derived from input_pos)
    const float* kc = (const float*)d_in[5];
    const float* vc = (const float*)d_in[6];
    const float* wq = (const float*)d_in[7];
    const float* wk = (const float*)d_in[8];
    const float* wv = (const float*)d_in[9];
    const float* wo = (const float*)d_in[10];
    float* out = (float*)d_out;

    cudaFuncSetAttribute(attn_kernel, cudaFuncAttributeMaxDynamicSharedMemorySize,
                         ATTN_SMEM_FLOATS * (int)sizeof(float));
    cudaFuncSetAttribute(qkv_kernel, cudaFuncAttributeMaxDynamicSharedMemorySize,
                         GEMM_SMEM_BYTES);
    cudaFuncSetAttribute(out_kernel, cudaFuncAttributeMaxDynamicSharedMemorySize,
                         GEMM_SMEM_BYTES);

    qkv_kernel<<<dim3(NTOT / 64, SPLITK), 256, GEMM_SMEM_BYTES>>>(x, wq, wk, wv);
    reduce_qkv_kernel<<<(M64 * NTOT / 4 + 255) / 256, 256>>>();
    rope_kernel<<<(QPAIRS + KPAIRS + 255) / 256, 256>>>(fc, fs);
    attn_kernel<<<NSPLIT * Bq * KVq, 256, ATTN_SMEM_FLOATS * sizeof(float)>>>(kc, vc, pos);
    combine_kernel<<<(Bq * KVq * AROWS * Dq + 255) / 256, 256>>>();
    out_kernel<<<dim3(DIMq / 64, SPLITK), 256, GEMM_SMEM_BYTES>>>(wo);
    reduce_out_kernel<<<(M64 * DIMq / 4 + 255) / 256, 256>>>(out);
}

// round 5
// speedup vs baseline: 2.6053x; 2.6053x over previous
#include <cuda_runtime.h>
#include <cuda_bf16.h>
#include <math.h>
#include <float.h>

// Problem constants
#define Bq   4
#define Tq   16
#define Sq   4096
#define Hq   32
#define KVq  8
#define Dq   128
#define DIMq 4096
#define HD   (Hq*Dq)          // 4096
#define KVD  (KVq*Dq)         // 1024
#define NTOT (HD + 2*KVD)     // 6144
#define M64  (Bq*Tq)          // 64
#define GQ   (Hq/KVq)         // 4
#define AROWS 64
#define NSPLIT 16
#define SCALE_F 0.08838834764831843f
#define SPLITK 4

// ---------------- scratch ----------------------------------------------------
__device__ float g_qkvp[SPLITK][M64 * NTOT];
__device__ float g_outp[SPLITK][M64 * DIMq];
__device__ float g_qkv [M64 * NTOT];
__device__ float g_qatt[Bq*KVq*AROWS*Dq];
__device__ float g_knew[M64*KVq*Dq];
__device__ float g_pacc[(size_t)NSPLIT*Bq*KVq*AROWS*Dq];
__device__ float g_pm  [NSPLIT*Bq*KVq*AROWS];
__device__ float g_pl  [NSPLIT*Bq*KVq*AROWS];
__device__ float g_y   [M64 * HD];

// ================= shared helpers ===========================================
__device__ __forceinline__ unsigned smem_u32(const void* p) {
    unsigned a;
    asm("{ .reg .u64 t; cvta.to.shared.u64 t, %1; cvt.u32.u64 %0, t; }"
        : "=r"(a) : "l"(p));
    return a;
}
__device__ __forceinline__ unsigned f2tf32(float x) {
    unsigned u; asm("cvt.rna.tf32.f32 %0, %1;" : "=r"(u) : "f"(x)); return u;
}
__device__ __forceinline__ void mma_tf32(float c[4], const unsigned a[4], const unsigned b[2]) {
    asm volatile(
        "mma.sync.aligned.m16n8k8.row.col.f32.tf32.tf32.f32 "
        "{%0,%1,%2,%3}, {%4,%5,%6,%7}, {%8,%9}, {%0,%1,%2,%3};\n"
        : "+f"(c[0]), "+f"(c[1]), "+f"(c[2]), "+f"(c[3])
        : "r"(a[0]), "r"(a[1]), "r"(a[2]), "r"(a[3]), "r"(b[0]), "r"(b[1]));
}
__device__ __forceinline__ void cpasync16(unsigned saddr, const float* g) {
    asm volatile("cp.async.ca.shared.global [%0], [%1], 16;" :: "r"(saddr), "l"(g));
}

// ================= tf32 split-K GEMM (unchanged from R3/R4) =================
#define BKg      32
#define GSTAGES  4
#define GSTRIDE  36
#define GSTG_FLT (2 * 64 * GSTRIDE)
#define GEMM_SMEM_BYTES (GSTAGES * GSTG_FLT * 4)
#define GK       4096
#define GNKS     (GK / BKg / SPLITK)

__device__ __forceinline__ void gemm_tile_mma(const float* __restrict__ A,
                                              const float* __restrict__ W,
                                              float* __restrict__ Cbase,
                                              int ldc, int kbeg) {
    extern __shared__ float smf[];
    const int tid  = threadIdx.x;
    const int lane = tid & 31;
    const int wid  = tid >> 5;
    const int gid  = lane >> 2;
    const int ctg  = lane & 3;
    const int wm   = wid & 1;
    const int wn   = wid >> 1;
    const int frow = tid >> 2;
    const int fk   = (tid & 3) * 8;
    const unsigned sbase = smem_u32(smf);

    float acc[2][2][4];
#pragma unroll
    for (int mi = 0; mi < 2; mi++)
#pragma unroll
        for (int ni = 0; ni < 2; ni++)
#pragma unroll
            for (int j = 0; j < 4; j++) acc[mi][ni][j] = 0.f;

#pragma unroll
    for (int s = 0; s < GSTAGES - 1; s++) {
        unsigned sa = sbase + (unsigned)(s * GSTG_FLT + frow * GSTRIDE + fk) * 4u;
        unsigned sw = sa + 64u * GSTRIDE * 4u;
        const float* ga = A + (size_t)frow * GK + kbeg + s * BKg + fk;
        const float* gw = W + (size_t)frow * GK + kbeg + s * BKg + fk;
        cpasync16(sa, ga);       cpasync16(sa + 16, ga + 4);
        cpasync16(sw, gw);       cpasync16(sw + 16, gw + 4);
        asm volatile("cp.async.commit_group;");
    }

    for (int i = 0; i < GNKS; i++) {
        asm volatile("cp.async.wait_group 2;");
        __syncthreads();
        const float* As = smf + (i & 3) * GSTG_FLT;
        const float* Ws = As + 64 * GSTRIDE;

#pragma unroll
        for (int ks = 0; ks < 4; ks++) {
            const int k = ks * 8;
            unsigned af[2][4], bf[2][2];
#pragma unroll
            for (int mi = 0; mi < 2; mi++) {
                int r = wm * 32 + mi * 16 + gid;
                af[mi][0] = f2tf32(As[r * GSTRIDE + k + ctg]);
                af[mi][1] = f2tf32(As[(r + 8) * GSTRIDE + k + ctg]);
                af[mi][2] = f2tf32(As[r * GSTRIDE + k + ctg + 4]);
                af[mi][3] = f2tf32(As[(r + 8) * GSTRIDE + k + ctg + 4]);
            }
#pragma unroll
            for (int ni = 0; ni < 2; ni++) {
                int n = wn * 16 + ni * 8 + gid;
                bf[ni][0] = f2tf32(Ws[n * GSTRIDE + k + ctg]);
                bf[ni][1] = f2tf32(Ws[n * GSTRIDE + k + ctg + 4]);
            }
#pragma unroll
            for (int mi = 0; mi < 2; mi++)
#pragma unroll
                for (int ni = 0; ni < 2; ni++)
                    mma_tf32(acc[mi][ni], af[mi], bf[ni]);
        }

        if (i + GSTAGES - 1 < GNKS) {
            int s = (i + 3) & 3;
            int k0 = kbeg + (i + 3) * BKg;
            unsigned sa = sbase + (unsigned)(s * GSTG_FLT + frow * GSTRIDE + fk) * 4u;
            unsigned sw = sa + 64u * GSTRIDE * 4u;
            const float* ga = A + (size_t)frow * GK + k0 + fk;
            const float* gw = W + (size_t)frow * GK + k0 + fk;
            cpasync16(sa, ga);       cpasync16(sa + 16, ga + 4);
            cpasync16(sw, gw);       cpasync16(sw + 16, gw + 4);
            asm volatile("cp.async.commit_group;");
        } else {
            asm volatile("cp.async.commit_group;");
        }
    }

#pragma unroll
    for (int mi = 0; mi < 2; mi++)
#pragma unroll
        for (int ni = 0; ni < 2; ni++) {
            int r0 = wm * 32 + mi * 16 + gid;
            int c0 = wn * 16 + ni * 8 + 2 * ctg;
            *reinterpret_cast<float2*>(&Cbase[(size_t)r0 * ldc + c0]) =
                make_float2(acc[mi][ni][0], acc[mi][ni][1]);
            *reinterpret_cast<float2*>(&Cbase[(size_t)(r0 + 8) * ldc + c0]) =
                make_float2(acc[mi][ni][2], acc[mi][ni][3]);
        }
}

__global__ void qkv_kernel(const float* __restrict__ x,
                           const float* __restrict__ wq,
                           const float* __restrict__ wk,
                           const float* __restrict__ wv) {
    int n0 = blockIdx.x * 64;
    int sp = blockIdx.y;
    const float* W;
    if (n0 < HD)            W = wq + (size_t)n0 * DIMq;
    else if (n0 < HD + KVD) W = wk + (size_t)(n0 - HD) * DIMq;
    else                    W = wv + (size_t)(n0 - HD - KVD) * DIMq;
    gemm_tile_mma(x, W, g_qkvp[sp] + n0, NTOT, sp * (GK / SPLITK));
}

__global__ void reduce_qkv_kernel() {
    int i = blockIdx.x * 256 + threadIdx.x;
    if (i >= M64 * NTOT / 4) return;
    float4 a = reinterpret_cast<const float4*>(g_qkvp[0])[i];
    float4 b = reinterpret_cast<const float4*>(g_qkvp[1])[i];
    float4 c = reinterpret_cast<const float4*>(g_qkvp[2])[i];
    float4 d = reinterpret_cast<const float4*>(g_qkvp[3])[i];
    reinterpret_cast<float4*>(g_qkv)[i] =
        make_float4(a.x+b.x+c.x+d.x, a.y+b.y+c.y+d.y,
                    a.z+b.z+c.z+d.z, a.w+b.w+c.w+d.w);
}

__global__ void out_kernel(const float* __restrict__ wo) {
    int n0 = blockIdx.x * 64;
    int sp = blockIdx.y;
    gemm_tile_mma(g_y, wo + (size_t)n0 * DIMq, g_outp[sp] + n0, DIMq,
                  sp * (GK / SPLITK));
}

__global__ void reduce_out_kernel(float* __restrict__ out) {
    int i = blockIdx.x * 256 + threadIdx.x;
    if (i >= M64 * DIMq / 4) return;
    float4 a = reinterpret_cast<const float4*>(g_outp[0])[i];
    float4 b = reinterpret_cast<const float4*>(g_outp[1])[i];
    float4 c = reinterpret_cast<const float4*>(g_outp[2])[i];
    float4 d = reinterpret_cast<const float4*>(g_outp[3])[i];
    reinterpret_cast<float4*>(out)[i] =
        make_float4(a.x+b.x+c.x+d.x, a.y+b.y+c.y+d.y,
                    a.z+b.z+c.z+d.z, a.w+b.w+c.w+d.w);
}

// ---------------- RoPE ------------------------------------------------------
#define QPAIRS (M64*Hq*(Dq/2))
#define KPAIRS (M64*KVq*(Dq/2))
__global__ void rope_kernel(const float* __restrict__ fc, const float* __restrict__ fs) {
    int idx = blockIdx.x * blockDim.x + threadIdx.x;
    if (idx < QPAIRS) {
        int i = idx & 63;
        int h = (idx >> 6) & (Hq - 1);
        int m = idx >> 11;
        int t = m & (Tq - 1), b = m >> 4;
        float c = fc[t * 64 + i], s = fs[t * 64 + i];
        const float* p = g_qkv + (size_t)m * NTOT + h * Dq + 2 * i;
        float x0 = p[0], x1 = p[1];
        int kv = h >> 2, hl = h & 3;
        float* q = g_qatt + ((((size_t)b * KVq + kv) * AROWS) + hl * Tq + t) * Dq + 2 * i;
        q[0] = (x0 * c - x1 * s) * SCALE_F;
        q[1] = (x0 * s + x1 * c) * SCALE_F;
    } else if (idx < QPAIRS + KPAIRS) {
        int j = idx - QPAIRS;
        int i = j & 63;
        int kv = (j >> 6) & (KVq - 1);
        int m = j >> 9;
        int t = m & (Tq - 1);
        float c = fc[t * 64 + i], s = fs[t * 64 + i];
        const float* p = g_qkv + (size_t)m * NTOT + HD + kv * Dq + 2 * i;
        float x0 = p[0], x1 = p[1];
        float* k = g_knew + ((size_t)m * KVq + kv) * Dq + 2 * i;
        k[0] = x0 * c - x1 * s;
        k[1] = x0 * s + x1 * c;
    }
}

// ================= tensor-core flash attention ===============================
// Per block: 64 q rows of one (b,kv), one KV split (chunk 32-aligned).
// All operands pre-converted to tf32 in smem; QK^T and P*V via mma m16n8k8.
// 8 warps: QK warp grid 4m x 2n (16x16 each of 64x32 scores);
//          PV warp grid 4m x 2n (16x64 each of 64x128 output).
#define QS 132   // Q row stride (tf32 bits)
#define KS 132   // K row stride
#define VS 136   // V row stride (disjoint bank groups for ctg)
#define PS 36    // P row stride
#define ATTN_SMEM_FLOATS (64*QS + 32*KS + 32*VS + 64*PS + 3*64)

__global__ void attn_kernel(const float* __restrict__ k_cache,
                            const float* __restrict__ v_cache,
                            const int* __restrict__ input_pos) {
    extern __shared__ float sm[];
    float*    Qs   = sm;                       // tf32 bits
    float*    Ks   = Qs + 64 * QS;             // tf32 bits
    float*    Vs   = Ks + 32 * KS;             // tf32 bits
    float*    Ps   = Vs + 32 * VS;             // scores (f32) then p (tf32 bits)
    float*    rowm = Ps + 64 * PS;
    float*    rowl = rowm + 64;
    float*    rowsc = rowl + 64;
    unsigned* QsU = reinterpret_cast<unsigned*>(Qs);
    unsigned* KsU = reinterpret_cast<unsigned*>(Ks);
    unsigned* VsU = reinterpret_cast<unsigned*>(Vs);
    unsigned* PsU = reinterpret_cast<unsigned*>(Ps);
    __shared__ int pos_s[Tq];

    const int tid  = threadIdx.x;
    const int lane = tid & 31;
    const int wid  = tid >> 5;
    const int gid  = lane >> 2;
    const int ctg  = lane & 3;
    const int wm   = wid & 3;       // m slab (16 rows)
    const int wn   = wid >> 2;      // n slab
    const int r0   = wm * 16 + gid; // fragment row (and r0+8)

    const int bk = blockIdx.x & 31;          // Bq*KVq = 32
    const int split = blockIdx.x >> 5;
    const int b = bk >> 3, kv = bk & 7;

    if (tid < Tq) pos_s[tid] = input_pos[tid];
    // load + cvt Q once
    {
        const float* qsrc = g_qatt + ((size_t)b * KVq + kv) * AROWS * Dq;
#pragma unroll
        for (int i = 0; i < 8; i++) {
            int e4 = tid + i * 256;              // 2048 float4
            int r = e4 >> 5, d4 = (e4 & 31) * 4;
            float4 v = *reinterpret_cast<const float4*>(&qsrc[r * Dq + d4]);
            uint4 u = make_uint4(f2tf32(v.x), f2tf32(v.y), f2tf32(v.z), f2tf32(v.w));
            *reinterpret_cast<uint4*>(&QsU[r * QS + d4]) = u;
        }
    }
    if (tid < AROWS) { rowm[tid] = -FLT_MAX; rowl[tid] = 0.f; }
    __syncthreads();

    const int limit = pos_s[Tq - 1] + 1;
    const int chunk = (((limit + NSPLIT - 1) / NSPLIT) + 31) & ~31;
    const int sbeg = split * chunk;
    const int send = min(sbeg + chunk, limit);
    const int start_pos = pos_s[0];

    float acc[8][4];
#pragma unroll
    for (int nt = 0; nt < 8; nt++)
#pragma unroll
        for (int j = 0; j < 4; j++) acc[nt][j] = 0.f;

    for (int s0 = sbeg; s0 < send; s0 += 32) {
        // ---- load K/V tile (cvt to tf32) ----
#pragma unroll
        for (int i = 0; i < 4; i++) {
            int e4 = tid + i * 256;              // 1024 float4 per operand
            int row = e4 >> 5, d4 = (e4 & 31) * 4;
            int s = s0 + row;
            float4 kf = make_float4(0.f, 0.f, 0.f, 0.f);
            float4 vf = make_float4(0.f, 0.f, 0.f, 0.f);
            if (s < send) {
                if (s >= start_pos) {
                    int mi = b * Tq + (s - start_pos);
                    kf = *reinterpret_cast<const float4*>(
                        &g_knew[((size_t)mi * KVq + kv) * Dq + d4]);
                    vf = *reinterpret_cast<const float4*>(
                        &g_qkv[(size_t)mi * NTOT + HD + KVD + kv * Dq + d4]);
                } else {
                    size_t base = (((size_t)b * Sq + s) * KVq + kv) * Dq + d4;
                    kf = *reinterpret_cast<const float4*>(&k_cache[base]);
                    vf = *reinterpret_cast<const float4*>(&v_cache[base]);
                }
            }
            *reinterpret_cast<uint4*>(&KsU[row * KS + d4]) =
                make_uint4(f2tf32(kf.x), f2tf32(kf.y), f2tf32(kf.z), f2tf32(kf.w));
            *reinterpret_cast<uint4*>(&VsU[row * VS + d4]) =
                make_uint4(f2tf32(vf.x), f2tf32(vf.y), f2tf32(vf.z), f2tf32(vf.w));
        }
        __syncthreads();

        // ---- QK^T: warp computes 16x16 of 64x32 ----
        float sc[2][4];
#pragma unroll
        for (int nt = 0; nt < 2; nt++)
#pragma unroll
            for (int j = 0; j < 4; j++) sc[nt][j] = 0.f;
#pragma unroll
        for (int ks = 0; ks < 16; ks++) {
            const int k = ks * 8;
            unsigned a[4];
            a[0] = QsU[r0 * QS + k + ctg];
            a[1] = QsU[(r0 + 8) * QS + k + ctg];
            a[2] = QsU[r0 * QS + k + ctg + 4];
            a[3] = QsU[(r0 + 8) * QS + k + ctg + 4];
#pragma unroll
            for (int nt = 0; nt < 2; nt++) {
                int n = wn * 16 + nt * 8 + gid;
                unsigned bfr[2];
                bfr[0] = KsU[n * KS + k + ctg];
                bfr[1] = KsU[n * KS + k + ctg + 4];
                mma_tf32(sc[nt], a, bfr);
            }
        }
        // masked score write
        {
            int t0 = r0 & 15, t1 = (r0 + 8) & 15;
            int p0 = pos_s[t0], p1 = pos_s[t1];
#pragma unroll
            for (int nt = 0; nt < 2; nt++) {
                int cb = wn * 16 + nt * 8 + 2 * ctg;
                int sA = s0 + cb, sB = s0 + cb + 1;
                Ps[r0 * PS + cb]         = (sA < send && sA <= p0) ? sc[nt][0] : -FLT_MAX;
                Ps[r0 * PS + cb + 1]     = (sB < send && sB <= p0) ? sc[nt][1] : -FLT_MAX;
                Ps[(r0 + 8) * PS + cb]     = (sA < send && sA <= p1) ? sc[nt][2] : -FLT_MAX;
                Ps[(r0 + 8) * PS + cb + 1] = (sB < send && sB <= p1) ? sc[nt][3] : -FLT_MAX;
            }
        }
        __syncthreads();

        // ---- online softmax: 4 threads per row ----
        {
            int r = tid >> 2, sub = tid & 3;
            float mx = -FLT_MAX;
#pragma unroll
            for (int j = 0; j < 8; j++)
                mx = fmaxf(mx, Ps[r * PS + sub * 8 + j]);
            mx = fmaxf(mx, __shfl_xor_sync(0xFFFFFFFF, mx, 1));
            mx = fmaxf(mx, __shfl_xor_sync(0xFFFFFFFF, mx, 2));
            float mold = rowm[r];
            float mnew = fmaxf(mold, mx);
            float lsum = 0.f;
#pragma unroll
            for (int j = 0; j < 8; j++) {
                float p = __expf(Ps[r * PS + sub * 8 + j] - mnew);
                unsigned pt = f2tf32(p);
                float ptf = __uint_as_float(pt);
                PsU[r * PS + sub * 8 + j] = pt;
                lsum += ptf;
            }
            lsum += __shfl_xor_sync(0xFFFFFFFF, lsum, 1);
            lsum += __shfl_xor_sync(0xFFFFFFFF, lsum, 2);
            if (sub == 0) {
                float scl = __expf(mold - mnew);
                rowsc[r] = scl;
                rowl[r] = rowl[r] * scl + lsum;
                rowm[r] = mnew;
            }
        }
        __syncthreads();

        // ---- rescale accumulators + P@V ----
        {
            float s0c = rowsc[r0], s1c = rowsc[r0 + 8];
#pragma unroll
            for (int nt = 0; nt < 8; nt++) {
                acc[nt][0] *= s0c; acc[nt][1] *= s0c;
                acc[nt][2] *= s1c; acc[nt][3] *= s1c;
            }
        }
#pragma unroll
        for (int ks = 0; ks < 4; ks++) {
            const int kk = ks * 8;
            unsigned a[4];
            a[0] = PsU[r0 * PS + kk + ctg];
            a[1] = PsU[(r0 + 8) * PS + kk + ctg];
            a[2] = PsU[r0 * PS + kk + ctg + 4];
            a[3] = PsU[(r0 + 8) * PS + kk + ctg + 4];
#pragma unroll
            for (int nt = 0; nt < 8; nt++) {
                int n = wn * 64 + nt * 8 + gid;
                unsigned bfr[2];
                bfr[0] = VsU[(kk + ctg) * VS + n];
                bfr[1] = VsU[(kk + ctg + 4) * VS + n];
                mma_tf32(acc[nt], a, bfr);
            }
        }
        __syncthreads();
    }

    // ---- write split partials ----
    {
        float* pbase = g_pacc + ((size_t)split * Bq * KVq + bk) * AROWS * Dq;
#pragma unroll
        for (int nt = 0; nt < 8; nt++) {
            int col = wn * 64 + nt * 8 + 2 * ctg;
            *reinterpret_cast<float2*>(&pbase[(size_t)r0 * Dq + col]) =
                make_float2(acc[nt][0], acc[nt][1]);
            *reinterpret_cast<float2*>(&pbase[(size_t)(r0 + 8) * Dq + col]) =
                make_float2(acc[nt][2], acc[nt][3]);
        }
    }
    if (tid < AROWS) {
        int o = (split * Bq * KVq + bk) * AROWS + tid;
        g_pm[o] = rowm[tid];
        g_pl[o] = rowl[tid];
    }
}

// ---------------- combine splits --------------------------------------------
__global__ void combine_kernel() {
    int idx = blockIdx.x * 256 + threadIdx.x;
    if (idx >= Bq * KVq * AROWS * Dq) return;
    int d = idx & 127;
    int r = (idx >> 7) & 63;
    int bk = idx >> 13;
    float M = -FLT_MAX;
#pragma unroll
    for (int sp = 0; sp < NSPLIT; sp++)
        M = fmaxf(M, g_pm[(sp * Bq * KVq + bk) * AROWS + r]);
    float L = 0.f, Y = 0.f;
#pragma unroll
    for (int sp = 0; sp < NSPLIT; sp++) {
        int o = (sp * Bq * KVq + bk) * AROWS + r;
        float w = __expf(g_pm[o] - M);
        L += g_pl[o] * w;
        Y += g_pacc[(size_t)o * Dq + d] * w;
    }
    float y = Y / L;
    int b = bk >> 3, kv = bk & 7;
    int hl = r >> 4, t = r & 15;
    int h = kv * GQ + hl;
    int m = b * Tq + t;
    g_y[(size_t)m * HD + h * Dq + d] = y;
}

// ---------------- launch -----------------------------------------------------
extern "C" void kernel_launch(void* const* d_in, const int* in_sizes, int n_in,
                              void* d_out, int out_size) {
    const float* x  = (const float*)d_in[0];
    const float* fc = (const float*)d_in[1];
    const float* fs = (const float*)d_in[2];
    const int*  pos = (const int*)  d_in[3];
    const float* kc = (const float*)d_in[5];
    const float* vc = (const float*)d_in[6];
    const float* wq = (const float*)d_in[7];
    const float* wk = (const float*)d_in[8];
    const float* wv = (const float*)d_in[9];
    const float* wo = (const float*)d_in[10];
    float* out = (float*)d_out;

    cudaFuncSetAttribute(attn_kernel, cudaFuncAttributeMaxDynamicSharedMemorySize,
                         ATTN_SMEM_FLOATS * (int)sizeof(float));
    cudaFuncSetAttribute(qkv_kernel, cudaFuncAttributeMaxDynamicSharedMemorySize,
                         GEMM_SMEM_BYTES);
    cudaFuncSetAttribute(out_kernel, cudaFuncAttributeMaxDynamicSharedMemorySize,
                         GEMM_SMEM_BYTES);

    qkv_kernel<<<dim3(NTOT / 64, SPLITK), 256, GEMM_SMEM_BYTES>>>(x, wq, wk, wv);
    reduce_qkv_kernel<<<(M64 * NTOT / 4 + 255) / 256, 256>>>();
    rope_kernel<<<(QPAIRS + KPAIRS + 255) / 256, 256>>>(fc, fs);
    attn_kernel<<<NSPLIT * Bq * KVq, 256, ATTN_SMEM_FLOATS * sizeof(float)>>>(kc, vc, pos);
    combine_kernel<<<(Bq * KVq * AROWS * Dq + 255) / 256, 256>>>();
    out_kernel<<<dim3(DIMq / 64, SPLITK), 256, GEMM_SMEM_BYTES>>>(wo);
    reduce_out_kernel<<<(M64 * DIMq / 4 + 255) / 256, 256>>>(out);
}

// round 6
// speedup vs baseline: 2.7129x; 1.0413x over previous
#include <cuda_runtime.h>
#include <cuda_bf16.h>
#include <math.h>
#include <float.h>

// Problem constants
#define Bq   4
#define Tq   16
#define Sq   4096
#define Hq   32
#define KVq  8
#define Dq   128
#define DIMq 4096
#define HD   (Hq*Dq)          // 4096
#define KVD  (KVq*Dq)         // 1024
#define NTOT (HD + 2*KVD)     // 6144
#define M64  (Bq*Tq)          // 64
#define GQ   (Hq/KVq)         // 4
#define AROWS 64
#define NSPLIT 16
#define SCALE_F 0.08838834764831843f
#define SPLITK  4             // qkv
#define SPLITKO 8             // out proj

// ---------------- scratch ----------------------------------------------------
__device__ float g_qkvp[SPLITK][M64 * NTOT];
__device__ float g_outp[SPLITKO][M64 * DIMq];
__device__ float g_qatt[Bq*KVq*AROWS*Dq];
__device__ float g_knew[M64*KVq*Dq];
__device__ float g_vnew[M64*KVD];
__device__ float g_pacc[(size_t)NSPLIT*Bq*KVq*AROWS*Dq];
__device__ float g_pm  [NSPLIT*Bq*KVq*AROWS];
__device__ float g_pl  [NSPLIT*Bq*KVq*AROWS];
__device__ float g_y   [M64 * HD];

// ================= shared helpers ===========================================
__device__ __forceinline__ unsigned smem_u32(const void* p) {
    unsigned a;
    asm("{ .reg .u64 t; cvta.to.shared.u64 t, %1; cvt.u32.u64 %0, t; }"
        : "=r"(a) : "l"(p));
    return a;
}
__device__ __forceinline__ unsigned f2tf32(float x) {
    unsigned u; asm("cvt.rna.tf32.f32 %0, %1;" : "=r"(u) : "f"(x)); return u;
}
__device__ __forceinline__ void mma_tf32(float c[4], const unsigned a[4], const unsigned b[2]) {
    asm volatile(
        "mma.sync.aligned.m16n8k8.row.col.f32.tf32.tf32.f32 "
        "{%0,%1,%2,%3}, {%4,%5,%6,%7}, {%8,%9}, {%0,%1,%2,%3};\n"
        : "+f"(c[0]), "+f"(c[1]), "+f"(c[2]), "+f"(c[3])
        : "r"(a[0]), "r"(a[1]), "r"(a[2]), "r"(a[3]), "r"(b[0]), "r"(b[1]));
}
__device__ __forceinline__ void cpasync16(unsigned saddr, const float* g) {
    asm volatile("cp.async.ca.shared.global [%0], [%1], 16;" :: "r"(saddr), "l"(g));
}
__device__ __forceinline__ uint4 cvt4(float4 v) {
    return make_uint4(f2tf32(v.x), f2tf32(v.y), f2tf32(v.z), f2tf32(v.w));
}

// ================= tf32 split-K GEMM, 64x128 block tile =====================
// 8 warps as 2m x 4n, warp tile 32x32 (2 x 4 of m16n8), BK=32, 4-stage cp.async.
#define BKg      32
#define GSTAGES  4
#define GSTRIDE  36
#define GSTG_FLT (192 * GSTRIDE)             // A(64) + W(128) rows per stage
#define GEMM_SMEM_BYTES (GSTAGES * GSTG_FLT * 4)   // 110592
#define GK       4096

__device__ __forceinline__ void gemm_tile_mma(const float* __restrict__ A,
                                              const float* __restrict__ W,
                                              float* __restrict__ Cbase,
                                              int ldc, int kbeg, int nks) {
    extern __shared__ float smf[];
    const int tid  = threadIdx.x;
    const int lane = tid & 31;
    const int wid  = tid >> 5;
    const int gid  = lane >> 2;
    const int ctg  = lane & 3;
    const int wm   = wid & 1;        // 32-row slab
    const int wn   = wid >> 1;       // 0..3, 32-col slab
    const int frA  = tid >> 2;       // 0..63
    const int fkA  = (tid & 3) * 8;
    const int frW  = tid >> 1;       // 0..127
    const int fkW  = (tid & 1) * 16;
    const unsigned sbase = smem_u32(smf);

    float acc[2][4][4];
#pragma unroll
    for (int mi = 0; mi < 2; mi++)
#pragma unroll
        for (int ni = 0; ni < 4; ni++)
#pragma unroll
            for (int j = 0; j < 4; j++) acc[mi][ni][j] = 0.f;

#pragma unroll
    for (int s = 0; s < GSTAGES - 1; s++) {
        unsigned sa = sbase + (unsigned)(s * GSTG_FLT + frA * GSTRIDE + fkA) * 4u;
        unsigned sw = sbase + (unsigned)(s * GSTG_FLT + (64 + frW) * GSTRIDE + fkW) * 4u;
        const float* ga = A + (size_t)frA * GK + kbeg + s * BKg + fkA;
        const float* gw = W + (size_t)frW * GK + kbeg + s * BKg + fkW;
        cpasync16(sa, ga);       cpasync16(sa + 16, ga + 4);
        cpasync16(sw, gw);       cpasync16(sw + 16, gw + 4);
        cpasync16(sw + 32, gw + 8); cpasync16(sw + 48, gw + 12);
        asm volatile("cp.async.commit_group;");
    }

    for (int i = 0; i < nks; i++) {
        asm volatile("cp.async.wait_group 2;");
        __syncthreads();
        const float* As = smf + (i & 3) * GSTG_FLT;
        const float* Ws = As + 64 * GSTRIDE;

#pragma unroll
        for (int ks = 0; ks < 4; ks++) {
            const int k = ks * 8;
            unsigned af[2][4], bf[4][2];
#pragma unroll
            for (int mi = 0; mi < 2; mi++) {
                int r = wm * 32 + mi * 16 + gid;
                af[mi][0] = f2tf32(As[r * GSTRIDE + k + ctg]);
                af[mi][1] = f2tf32(As[(r + 8) * GSTRIDE + k + ctg]);
                af[mi][2] = f2tf32(As[r * GSTRIDE + k + ctg + 4]);
                af[mi][3] = f2tf32(As[(r + 8) * GSTRIDE + k + ctg + 4]);
            }
#pragma unroll
            for (int ni = 0; ni < 4; ni++) {
                int n = wn * 32 + ni * 8 + gid;
                bf[ni][0] = f2tf32(Ws[n * GSTRIDE + k + ctg]);
                bf[ni][1] = f2tf32(Ws[n * GSTRIDE + k + ctg + 4]);
            }
#pragma unroll
            for (int mi = 0; mi < 2; mi++)
#pragma unroll
                for (int ni = 0; ni < 4; ni++)
                    mma_tf32(acc[mi][ni], af[mi], bf[ni]);
        }

        if (i + GSTAGES - 1 < nks) {
            int s = (i + 3) & 3;
            int k0 = kbeg + (i + 3) * BKg;
            unsigned sa = sbase + (unsigned)(s * GSTG_FLT + frA * GSTRIDE + fkA) * 4u;
            unsigned sw = sbase + (unsigned)(s * GSTG_FLT + (64 + frW) * GSTRIDE + fkW) * 4u;
            const float* ga = A + (size_t)frA * GK + k0 + fkA;
            const float* gw = W + (size_t)frW * GK + k0 + fkW;
            cpasync16(sa, ga);       cpasync16(sa + 16, ga + 4);
            cpasync16(sw, gw);       cpasync16(sw + 16, gw + 4);
            cpasync16(sw + 32, gw + 8); cpasync16(sw + 48, gw + 12);
            asm volatile("cp.async.commit_group;");
        } else {
            asm volatile("cp.async.commit_group;");
        }
    }

#pragma unroll
    for (int mi = 0; mi < 2; mi++)
#pragma unroll
        for (int ni = 0; ni < 4; ni++) {
            int r0 = wm * 32 + mi * 16 + gid;
            int c0 = wn * 32 + ni * 8 + 2 * ctg;
            *reinterpret_cast<float2*>(&Cbase[(size_t)r0 * ldc + c0]) =
                make_float2(acc[mi][ni][0], acc[mi][ni][1]);
            *reinterpret_cast<float2*>(&Cbase[(size_t)(r0 + 8) * ldc + c0]) =
                make_float2(acc[mi][ni][2], acc[mi][ni][3]);
        }
}

__global__ void qkv_kernel(const float* __restrict__ x,
                           const float* __restrict__ wq,
                           const float* __restrict__ wk,
                           const float* __restrict__ wv) {
    int n0 = blockIdx.x * 128;
    int sp = blockIdx.y;
    const float* W;
    if (n0 < HD)            W = wq + (size_t)n0 * DIMq;
    else if (n0 < HD + KVD) W = wk + (size_t)(n0 - HD) * DIMq;
    else                    W = wv + (size_t)(n0 - HD - KVD) * DIMq;
    gemm_tile_mma(x, W, g_qkvp[sp] + n0, NTOT, sp * (GK / SPLITK), GK / BKg / SPLITK);
}

__global__ void out_kernel(const float* __restrict__ wo) {
    int n0 = blockIdx.x * 128;
    int sp = blockIdx.y;
    gemm_tile_mma(g_y, wo + (size_t)n0 * DIMq, g_outp[sp] + n0, DIMq,
                  sp * (GK / SPLITKO), GK / BKg / SPLITKO);
}

__global__ void reduce_out_kernel(float* __restrict__ out) {
    int i = blockIdx.x * 256 + threadIdx.x;
    if (i >= M64 * DIMq / 4) return;
    float4 r = reinterpret_cast<const float4*>(g_outp[0])[i];
#pragma unroll
    for (int sp = 1; sp < SPLITKO; sp++) {
        float4 v = reinterpret_cast<const float4*>(g_outp[sp])[i];
        r.x += v.x; r.y += v.y; r.z += v.z; r.w += v.w;
    }
    reinterpret_cast<float4*>(out)[i] = r;
}

// ---------------- fused split-K reduce + RoPE -------------------------------
#define QPAIRS (M64*Hq*(Dq/2))   // 131072
#define KPAIRS (M64*KVq*(Dq/2))  // 32768
#define VQUADS (M64*KVD/4)       // 16384
__global__ void rope_fused_kernel(const float* __restrict__ fc,
                                  const float* __restrict__ fs) {
    int idx = blockIdx.x * blockDim.x + threadIdx.x;
    if (idx < QPAIRS) {
        int i = idx & 63;
        int h = (idx >> 6) & (Hq - 1);
        int m = idx >> 11;
        int t = m & (Tq - 1), b = m >> 4;
        size_t off = (size_t)m * NTOT + h * Dq + 2 * i;
        float x0 = 0.f, x1 = 0.f;
#pragma unroll
        for (int sp = 0; sp < SPLITK; sp++) {
            float2 p = *reinterpret_cast<const float2*>(&g_qkvp[sp][off]);
            x0 += p.x; x1 += p.y;
        }
        float c = fc[t * 64 + i], s = fs[t * 64 + i];
        int kv = h >> 2, hl = h & 3;
        float* q = g_qatt + ((((size_t)b * KVq + kv) * AROWS) + hl * Tq + t) * Dq + 2 * i;
        q[0] = (x0 * c - x1 * s) * SCALE_F;
        q[1] = (x0 * s + x1 * c) * SCALE_F;
    } else if (idx < QPAIRS + KPAIRS) {
        int j = idx - QPAIRS;
        int i = j & 63;
        int kv = (j >> 6) & (KVq - 1);
        int m = j >> 9;
        int t = m & (Tq - 1);
        size_t off = (size_t)m * NTOT + HD + kv * Dq + 2 * i;
        float x0 = 0.f, x1 = 0.f;
#pragma unroll
        for (int sp = 0; sp < SPLITK; sp++) {
            float2 p = *reinterpret_cast<const float2*>(&g_qkvp[sp][off]);
            x0 += p.x; x1 += p.y;
        }
        float c = fc[t * 64 + i], s = fs[t * 64 + i];
        float* k = g_knew + ((size_t)m * KVq + kv) * Dq + 2 * i;
        k[0] = x0 * c - x1 * s;
        k[1] = x0 * s + x1 * c;
    } else if (idx < QPAIRS + KPAIRS + VQUADS) {
        int j = idx - (QPAIRS + KPAIRS);
        int m = j >> 8;               // KVD/4 = 256 float4 per m
        int c4 = (j & 255) * 4;
        size_t off = (size_t)m * NTOT + HD + KVD + c4;
        float4 r = make_float4(0.f, 0.f, 0.f, 0.f);
#pragma unroll
        for (int sp = 0; sp < SPLITK; sp++) {
            float4 v = *reinterpret_cast<const float4*>(&g_qkvp[sp][off]);
            r.x += v.x; r.y += v.y; r.z += v.z; r.w += v.w;
        }
        *reinterpret_cast<float4*>(&g_vnew[(size_t)m * KVD + c4]) = r;
    }
}

// ================= tensor-core flash attention (reg-prefetched KV) ==========
#define QS 132
#define KS 132
#define VS 136
#define PS 36
#define ATTN_SMEM_FLOATS (64*QS + 32*KS + 32*VS + 64*PS + 3*64)

__global__ void __launch_bounds__(256, 2)
attn_kernel(const float* __restrict__ k_cache,
            const float* __restrict__ v_cache,
            const int* __restrict__ input_pos) {
    extern __shared__ float sm[];
    float*    Qs   = sm;
    float*    Ks   = Qs + 64 * QS;
    float*    Vs   = Ks + 32 * KS;
    float*    Ps   = Vs + 32 * VS;
    float*    rowm = Ps + 64 * PS;
    float*    rowl = rowm + 64;
    float*    rowsc = rowl + 64;
    unsigned* QsU = reinterpret_cast<unsigned*>(Qs);
    unsigned* KsU = reinterpret_cast<unsigned*>(Ks);
    unsigned* VsU = reinterpret_cast<unsigned*>(Vs);
    unsigned* PsU = reinterpret_cast<unsigned*>(Ps);
    __shared__ int pos_s[Tq];

    const int tid  = threadIdx.x;
    const int lane = tid & 31;
    const int wid  = tid >> 5;
    const int gid  = lane >> 2;
    const int ctg  = lane & 3;
    const int wm   = wid & 3;
    const int wn   = wid >> 2;
    const int r0   = wm * 16 + gid;

    const int bk = blockIdx.x & 31;
    const int split = blockIdx.x >> 5;
    const int b = bk >> 3, kv = bk & 7;

    if (tid < Tq) pos_s[tid] = input_pos[tid];
    {
        const float* qsrc = g_qatt + ((size_t)b * KVq + kv) * AROWS * Dq;
#pragma unroll
        for (int i = 0; i < 8; i++) {
            int e4 = tid + i * 256;
            int r = e4 >> 5, d4 = (e4 & 31) * 4;
            float4 v = *reinterpret_cast<const float4*>(&qsrc[r * Dq + d4]);
            *reinterpret_cast<uint4*>(&QsU[r * QS + d4]) = cvt4(v);
        }
    }
    if (tid < AROWS) { rowm[tid] = -FLT_MAX; rowl[tid] = 0.f; }
    __syncthreads();

    const int limit = pos_s[Tq - 1] + 1;
    const int chunk = (((limit + NSPLIT - 1) / NSPLIT) + 31) & ~31;
    const int sbeg = split * chunk;
    const int send = min(sbeg + chunk, limit);
    const int start_pos = pos_s[0];

    const int prow = tid >> 5;          // base row for prefetch
    const int pd4  = (tid & 31) * 4;

    float4 kf[4], vf[4];
    // prefetch first tile
    {
        int s0 = sbeg;
#pragma unroll
        for (int i = 0; i < 4; i++) {
            int s = s0 + prow + i * 8;
            float4 kv_ = make_float4(0.f,0.f,0.f,0.f);
            float4 vv_ = make_float4(0.f,0.f,0.f,0.f);
            if (s < send) {
                if (s >= start_pos) {
                    int mi = b * Tq + (s - start_pos);
                    kv_ = *reinterpret_cast<const float4*>(
                        &g_knew[((size_t)mi * KVq + kv) * Dq + pd4]);
                    vv_ = *reinterpret_cast<const float4*>(
                        &g_vnew[(size_t)mi * KVD + kv * Dq + pd4]);
                } else {
                    size_t base = (((size_t)b * Sq + s) * KVq + kv) * Dq + pd4;
                    kv_ = *reinterpret_cast<const float4*>(&k_cache[base]);
                    vv_ = *reinterpret_cast<const float4*>(&v_cache[base]);
                }
            }
            kf[i] = kv_; vf[i] = vv_;
        }
    }

    float acc[8][4];
#pragma unroll
    for (int nt = 0; nt < 8; nt++)
#pragma unroll
        for (int j = 0; j < 4; j++) acc[nt][j] = 0.f;

    for (int s0 = sbeg; s0 < send; s0 += 32) {
        // ---- store prefetched tile (cvt to tf32) ----
#pragma unroll
        for (int i = 0; i < 4; i++) {
            int row = prow + i * 8;
            *reinterpret_cast<uint4*>(&KsU[row * KS + pd4]) = cvt4(kf[i]);
            *reinterpret_cast<uint4*>(&VsU[row * VS + pd4]) = cvt4(vf[i]);
        }
        __syncthreads();

        // ---- prefetch next tile (independent; hides behind mma) ----
        if (s0 + 32 < send) {
            int sn = s0 + 32;
#pragma unroll
            for (int i = 0; i < 4; i++) {
                int s = sn + prow + i * 8;
                float4 kv_ = make_float4(0.f,0.f,0.f,0.f);
                float4 vv_ = make_float4(0.f,0.f,0.f,0.f);
                if (s < send) {
                    if (s >= start_pos) {
                        int mi = b * Tq + (s - start_pos);
                        kv_ = *reinterpret_cast<const float4*>(
                            &g_knew[((size_t)mi * KVq + kv) * Dq + pd4]);
                        vv_ = *reinterpret_cast<const float4*>(
                            &g_vnew[(size_t)mi * KVD + kv * Dq + pd4]);
                    } else {
                        size_t base = (((size_t)b * Sq + s) * KVq + kv) * Dq + pd4;
                        kv_ = *reinterpret_cast<const float4*>(&k_cache[base]);
                        vv_ = *reinterpret_cast<const float4*>(&v_cache[base]);
                    }
                }
                kf[i] = kv_; vf[i] = vv_;
            }
        }

        // ---- QK^T: warp computes 16x16 of 64x32 ----
        float sc[2][4];
#pragma unroll
        for (int nt = 0; nt < 2; nt++)
#pragma unroll
            for (int j = 0; j < 4; j++) sc[nt][j] = 0.f;
#pragma unroll
        for (int ks = 0; ks < 16; ks++) {
            const int k = ks * 8;
            unsigned a[4];
            a[0] = QsU[r0 * QS + k + ctg];
            a[1] = QsU[(r0 + 8) * QS + k + ctg];
            a[2] = QsU[r0 * QS + k + ctg + 4];
            a[3] = QsU[(r0 + 8) * QS + k + ctg + 4];
#pragma unroll
            for (int nt = 0; nt < 2; nt++) {
                int n = wn * 16 + nt * 8 + gid;
                unsigned bfr[2];
                bfr[0] = KsU[n * KS + k + ctg];
                bfr[1] = KsU[n * KS + k + ctg + 4];
                mma_tf32(sc[nt], a, bfr);
            }
        }
        {
            int t0 = r0 & 15, t1 = (r0 + 8) & 15;
            int p0 = pos_s[t0], p1 = pos_s[t1];
#pragma unroll
            for (int nt = 0; nt < 2; nt++) {
                int cb = wn * 16 + nt * 8 + 2 * ctg;
                int sA = s0 + cb, sB = s0 + cb + 1;
                Ps[r0 * PS + cb]           = (sA < send && sA <= p0) ? sc[nt][0] : -FLT_MAX;
                Ps[r0 * PS + cb + 1]       = (sB < send && sB <= p0) ? sc[nt][1] : -FLT_MAX;
                Ps[(r0 + 8) * PS + cb]     = (sA < send && sA <= p1) ? sc[nt][2] : -FLT_MAX;
                Ps[(r0 + 8) * PS + cb + 1] = (sB < send && sB <= p1) ? sc[nt][3] : -FLT_MAX;
            }
        }
        __syncthreads();

        // ---- online softmax: 4 threads per row ----
        {
            int r = tid >> 2, sub = tid & 3;
            float mx = -FLT_MAX;
#pragma unroll
            for (int j = 0; j < 8; j++)
                mx = fmaxf(mx, Ps[r * PS + sub * 8 + j]);
            mx = fmaxf(mx, __shfl_xor_sync(0xFFFFFFFF, mx, 1));
            mx = fmaxf(mx, __shfl_xor_sync(0xFFFFFFFF, mx, 2));
            float mold = rowm[r];
            float mnew = fmaxf(mold, mx);
            float lsum = 0.f;
#pragma unroll
            for (int j = 0; j < 8; j++) {
                float p = __expf(Ps[r * PS + sub * 8 + j] - mnew);
                unsigned pt = f2tf32(p);
                PsU[r * PS + sub * 8 + j] = pt;
                lsum += __uint_as_float(pt);
            }
            lsum += __shfl_xor_sync(0xFFFFFFFF, lsum, 1);
            lsum += __shfl_xor_sync(0xFFFFFFFF, lsum, 2);
            if (sub == 0) {
                float scl = __expf(mold - mnew);
                rowsc[r] = scl;
                rowl[r] = rowl[r] * scl + lsum;
                rowm[r] = mnew;
            }
        }
        __syncthreads();

        // ---- rescale + P@V ----
        {
            float s0c = rowsc[r0], s1c = rowsc[r0 + 8];
#pragma unroll
            for (int nt = 0; nt < 8; nt++) {
                acc[nt][0] *= s0c; acc[nt][1] *= s0c;
                acc[nt][2] *= s1c; acc[nt][3] *= s1c;
            }
        }
#pragma unroll
        for (int ks = 0; ks < 4; ks++) {
            const int kk = ks * 8;
            unsigned a[4];
            a[0] = PsU[r0 * PS + kk + ctg];
            a[1] = PsU[(r0 + 8) * PS + kk + ctg];
            a[2] = PsU[r0 * PS + kk + ctg + 4];
            a[3] = PsU[(r0 + 8) * PS + kk + ctg + 4];
#pragma unroll
            for (int nt = 0; nt < 8; nt++) {
                int n = wn * 64 + nt * 8 + gid;
                unsigned bfr[2];
                bfr[0] = VsU[(kk + ctg) * VS + n];
                bfr[1] = VsU[(kk + ctg + 4) * VS + n];
                mma_tf32(acc[nt], a, bfr);
            }
        }
        __syncthreads();
    }

    {
        float* pbase = g_pacc + ((size_t)split * Bq * KVq + bk) * AROWS * Dq;
#pragma unroll
        for (int nt = 0; nt < 8; nt++) {
            int col = wn * 64 + nt * 8 + 2 * ctg;
            *reinterpret_cast<float2*>(&pbase[(size_t)r0 * Dq + col]) =
                make_float2(acc[nt][0], acc[nt][1]);
            *reinterpret_cast<float2*>(&pbase[(size_t)(r0 + 8) * Dq + col]) =
                make_float2(acc[nt][2], acc[nt][3]);
        }
    }
    if (tid < AROWS) {
        int o = (split * Bq * KVq + bk) * AROWS + tid;
        g_pm[o] = rowm[tid];
        g_pl[o] = rowl[tid];
    }
}

// ---------------- combine splits --------------------------------------------
__global__ void combine_kernel() {
    int idx = blockIdx.x * 256 + threadIdx.x;
    if (idx >= Bq * KVq * AROWS * Dq) return;
    int d = idx & 127;
    int r = (idx >> 7) & 63;
    int bk = idx >> 13;
    float M = -FLT_MAX;
#pragma unroll
    for (int sp = 0; sp < NSPLIT; sp++)
        M = fmaxf(M, g_pm[(sp * Bq * KVq + bk) * AROWS + r]);
    float L = 0.f, Y = 0.f;
#pragma unroll
    for (int sp = 0; sp < NSPLIT; sp++) {
        int o = (sp * Bq * KVq + bk) * AROWS + r;
        float w = __expf(g_pm[o] - M);
        L += g_pl[o] * w;
        Y += g_pacc[(size_t)o * Dq + d] * w;
    }
    float y = Y / L;
    int b = bk >> 3, kv = bk & 7;
    int hl = r >> 4, t = r & 15;
    int h = kv * GQ + hl;
    int m = b * Tq + t;
    g_y[(size_t)m * HD + h * Dq + d] = y;
}

// ---------------- launch -----------------------------------------------------
extern "C" void kernel_launch(void* const* d_in, const int* in_sizes, int n_in,
                              void* d_out, int out_size) {
    const float* x  = (const float*)d_in[0];
    const float* fc = (const float*)d_in[1];
    const float* fs = (const float*)d_in[2];
    const int*  pos = (const int*)  d_in[3];
    const float* kc = (const float*)d_in[5];
    const float* vc = (const float*)d_in[6];
    const float* wq = (const float*)d_in[7];
    const float* wk = (const float*)d_in[8];
    const float* wv = (const float*)d_in[9];
    const float* wo = (const float*)d_in[10];
    float* out = (float*)d_out;

    cudaFuncSetAttribute(attn_kernel, cudaFuncAttributeMaxDynamicSharedMemorySize,
                         ATTN_SMEM_FLOATS * (int)sizeof(float));
    cudaFuncSetAttribute(qkv_kernel, cudaFuncAttributeMaxDynamicSharedMemorySize,
                         GEMM_SMEM_BYTES);
    cudaFuncSetAttribute(out_kernel, cudaFuncAttributeMaxDynamicSharedMemorySize,
                         GEMM_SMEM_BYTES);

    qkv_kernel<<<dim3(NTOT / 128, SPLITK), 256, GEMM_SMEM_BYTES>>>(x, wq, wk, wv);
    rope_fused_kernel<<<(QPAIRS + KPAIRS + VQUADS + 255) / 256, 256>>>(fc, fs);
    attn_kernel<<<NSPLIT * Bq * KVq, 256, ATTN_SMEM_FLOATS * sizeof(float)>>>(kc, vc, pos);
    combine_kernel<<<(Bq * KVq * AROWS * Dq + 255) / 256, 256>>>();
    out_kernel<<<dim3(DIMq / 128, SPLITKO), 256, GEMM_SMEM_BYTES>>>(wo);
    reduce_out_kernel<<<(M64 * DIMq / 4 + 255) / 256, 256>>>(out);
}